// round 1
// baseline (speedup 1.0000x reference)
#include <cuda_runtime.h>
#include <cuda_bf16.h>
#include <math.h>

// Problem constants
#define Bb   4
#define Cc   64
#define Hh   96
#define Ww   96
#define HW   (Hh*Ww)            // 9216
#define Oo   64
#define Kk   9
#define CIN3 (3*Cc)             // 192
#define KTOT (CIN3*Kk)          // 1728
#define NPIX (Bb*HW)            // 36864
#define IMG  (Cc*HW)            // 589824 floats per batch per 64-ch tensor

// Scratch (no cudaMalloc allowed)
__device__ float g_offset[Bb * 2 * Kk * HW];   // [4][18][96][96]
__device__ float g_wT[KTOT * Oo];              // [ck][o]

// ---------------------------------------------------------------------------
// Kernel 1: diff = (ref - dist)^2  (also the second output tensor)
// ---------------------------------------------------------------------------
__global__ void diff_kernel(const float* __restrict__ ref,
                            const float* __restrict__ dist,
                            float* __restrict__ out_diff) {
    int i = blockIdx.x * blockDim.x + threadIdx.x;
    if (i < Bb * IMG) {
        float d = ref[i] - dist[i];
        out_diff[i] = d * d;
    }
}

// ---------------------------------------------------------------------------
// Kernel 2: offset conv3x3  (Cin=64 -> Cout=18), pad 1, stride 1
// one thread per pixel, 18 accumulators in regs, all weights in smem
// smem weight layout: [c*9+k][o] row stride 20 floats (16B aligned rows)
// ---------------------------------------------------------------------------
__global__ __launch_bounds__(256) void offset_conv_kernel(
        const float* __restrict__ ref,
        const float* __restrict__ ow,     // [18][64][3][3]
        const float* __restrict__ ob,     // [18]
        float* __restrict__ out) {        // g_offset
    __shared__ __align__(16) float s_w[576 * 20];
    int tid = threadIdx.x;
    for (int i = tid; i < 18 * 576; i += 256) {
        int o  = i / 576;
        int ck = i % 576;
        s_w[ck * 20 + o] = ow[i];
    }
    __syncthreads();

    int p = blockIdx.x * 256 + tid;          // 144 blocks * 256 = 36864 exactly
    int b = p / HW;
    int pix = p % HW;
    int y = pix / Ww;
    int x = pix % Ww;

    // precompute 3x3 neighbor indices + validity
    int  idx9[9];
    bool ok9[9];
#pragma unroll
    for (int ky = 0; ky < 3; ky++)
#pragma unroll
        for (int kx = 0; kx < 3; kx++) {
            int yy = y + ky - 1, xx = x + kx - 1;
            bool ok = (yy >= 0) && (yy < Hh) && (xx >= 0) && (xx < Ww);
            ok9[ky * 3 + kx] = ok;
            idx9[ky * 3 + kx] = (ok ? yy : 0) * Ww + (ok ? xx : 0);
        }

    float acc[18];
#pragma unroll
    for (int o = 0; o < 18; o++) acc[o] = 0.f;

    const float* xb = ref + b * IMG;
    for (int c = 0; c < Cc; c++) {
        const float* xc = xb + c * HW;
#pragma unroll
        for (int k = 0; k < 9; k++) {
            float v = ok9[k] ? __ldg(xc + idx9[k]) : 0.f;
            int base = (c * 9 + k) * 20;
            float4 w0 = *(const float4*)&s_w[base];
            float4 w1 = *(const float4*)&s_w[base + 4];
            float4 w2 = *(const float4*)&s_w[base + 8];
            float4 w3 = *(const float4*)&s_w[base + 12];
            float  wa = s_w[base + 16];
            float  wb = s_w[base + 17];
            acc[0]  += v * w0.x;  acc[1]  += v * w0.y;  acc[2]  += v * w0.z;  acc[3]  += v * w0.w;
            acc[4]  += v * w1.x;  acc[5]  += v * w1.y;  acc[6]  += v * w1.z;  acc[7]  += v * w1.w;
            acc[8]  += v * w2.x;  acc[9]  += v * w2.y;  acc[10] += v * w2.z;  acc[11] += v * w2.w;
            acc[12] += v * w3.x;  acc[13] += v * w3.y;  acc[14] += v * w3.z;  acc[15] += v * w3.w;
            acc[16] += v * wa;    acc[17] += v * wb;
        }
    }
#pragma unroll
    for (int o = 0; o < 18; o++) {
        out[(b * 18 + o) * HW + pix] = acc[o] + __ldg(ob + o);
    }
}

// ---------------------------------------------------------------------------
// Kernel 3: transpose deform weights [64][192*9] -> wT[ck][64]
// ---------------------------------------------------------------------------
__global__ void wtrans_kernel(const float* __restrict__ dw, float* __restrict__ wT) {
    int i = blockIdx.x * blockDim.x + threadIdx.x;
    if (i < KTOT * Oo) {
        int o  = i % Oo;
        int ck = i / Oo;
        wT[i] = dw[o * KTOT + ck];
    }
}

// ---------------------------------------------------------------------------
// Kernel 4: fused deformable conv (implicit GEMM) + bias + relu
// Block: 64 pixels (M) x 64 outputs (N), 256 threads (16x16), 4x4 microtile.
// K loop over 192 channels in chunks of 4 (-> 36 k-steps per chunk).
// ---------------------------------------------------------------------------
__global__ __launch_bounds__(256) void deform_kernel(
        const float* __restrict__ ref,
        const float* __restrict__ dist,
        const float* __restrict__ diffp,   // d_out + B*IMG
        const float* __restrict__ db,      // [64]
        float* __restrict__ out) {         // feat, d_out
    // bilinear meta: layout [tap][k*64 + p]  (conflict-free reads)
    __shared__ float s_tw[4 * 576];
    __shared__ int   s_ti[4 * 576];
    __shared__ __align__(16) float As[36][64];
    __shared__ __align__(16) float Ws[36][64];

    int tid = threadIdx.x;
    int p0  = blockIdx.x * 64;          // 576 blocks
    int b   = p0 / HW;                  // uniform per block (144 tiles/image)
    int pix0 = p0 % HW;

    const float* ref_b  = ref   + b * IMG;
    const float* dist_b = dist  + b * IMG;
    const float* diff_b = diffp + b * IMG;

    // ---- compute bilinear sampling metadata for 64 pixels x 9 kernel pos ----
    for (int i = tid; i < 576; i += 256) {
        int k = i / 64;
        int p = i % 64;
        int pix = pix0 + p;
        int y = pix / Ww;
        int x = pix % Ww;
        int ky = k / 3, kx = k % 3;
        float offy = g_offset[(b * 18 + 2 * k)     * HW + pix];
        float offx = g_offset[(b * 18 + 2 * k + 1) * HW + pix];
        float py = (float)(y - 1 + ky) + offy;
        float px = (float)(x - 1 + kx) + offx;
        float fy = floorf(py), fx = floorf(px);
        int y0 = (int)fy, x0 = (int)fx;
        float dy = py - fy, dx = px - fx;
#pragma unroll
        for (int t = 0; t < 4; t++) {
            int yt = y0 + (t >> 1);
            int xt = x0 + (t & 1);
            float wt = ((t >> 1) ? dy : (1.f - dy)) * ((t & 1) ? dx : (1.f - dx));
            bool valid = (yt >= 0) && (yt < Hh) && (xt >= 0) && (xt < Ww);
            int yc = yt < 0 ? 0 : (yt > Hh - 1 ? Hh - 1 : yt);
            int xc2 = xt < 0 ? 0 : (xt > Ww - 1 ? Ww - 1 : xt);
            s_tw[t * 576 + i] = valid ? wt : 0.f;
            s_ti[t * 576 + i] = yc * Ww + xc2;
        }
    }

    float acc[4][4];
#pragma unroll
    for (int a = 0; a < 4; a++)
#pragma unroll
        for (int c = 0; c < 4; c++) acc[a][c] = 0.f;

    int tx = tid % 16;  // pixel group
    int ty = tid / 16;  // output group

    for (int c0 = 0; c0 < CIN3; c0 += 4) {
        __syncthreads();   // previous GEMM done (and meta on first iter)
        // stage weight tile: rows c0*9 .. c0*9+35 of wT, contiguous
        {
            const float* src = g_wT + c0 * 9 * Oo;
            float* dst = &Ws[0][0];
            for (int i = tid; i < 36 * 64; i += 256) dst[i] = __ldg(src + i);
        }
        // build sampled A tile: As[ck][p], ck = c_local*9 + k
        for (int i = tid; i < 4 * 9 * 64; i += 256) {
            int p  = i % 64;
            int ck = i / 64;
            int cl = ck / 9;
            int k  = ck % 9;
            int c  = c0 + cl;
            const float* src;
            if (c < Cc)            src = ref_b  + c * HW;
            else if (c < 2 * Cc)   src = dist_b + (c - Cc) * HW;
            else                   src = diff_b + (c - 2 * Cc) * HW;
            int m = k * 64 + p;
            float v = s_tw[m]            * __ldg(src + s_ti[m])
                    + s_tw[576 + m]      * __ldg(src + s_ti[576 + m])
                    + s_tw[2 * 576 + m]  * __ldg(src + s_ti[2 * 576 + m])
                    + s_tw[3 * 576 + m]  * __ldg(src + s_ti[3 * 576 + m]);
            As[ck][p] = v;
        }
        __syncthreads();
        // GEMM microkernel: 36 k-steps, 4x4 per thread
#pragma unroll
        for (int kk = 0; kk < 36; kk++) {
            float4 a  = *(const float4*)&As[kk][tx * 4];
            float4 w  = *(const float4*)&Ws[kk][ty * 4];
            acc[0][0] += w.x * a.x; acc[0][1] += w.x * a.y; acc[0][2] += w.x * a.z; acc[0][3] += w.x * a.w;
            acc[1][0] += w.y * a.x; acc[1][1] += w.y * a.y; acc[1][2] += w.y * a.z; acc[1][3] += w.y * a.w;
            acc[2][0] += w.z * a.x; acc[2][1] += w.z * a.y; acc[2][2] += w.z * a.z; acc[2][3] += w.z * a.w;
            acc[3][0] += w.w * a.x; acc[3][1] += w.w * a.y; acc[3][2] += w.w * a.z; acc[3][3] += w.w * a.w;
        }
    }

    // epilogue: bias + relu, out[b][o][pix]
#pragma unroll
    for (int oo = 0; oo < 4; oo++) {
        int o = ty * 4 + oo;
        float bias = __ldg(db + o);
        float* orow = out + (b * Oo + o) * HW + pix0;
#pragma unroll
        for (int pp = 0; pp < 4; pp++) {
            int pl = tx * 4 + pp;
            float v = acc[oo][pp] + bias;
            orow[pl] = v > 0.f ? v : 0.f;
        }
    }
}

// ---------------------------------------------------------------------------
extern "C" void kernel_launch(void* const* d_in, const int* in_sizes, int n_in,
                              void* d_out, int out_size) {
    const float* ref  = (const float*)d_in[0];
    const float* dist = (const float*)d_in[1];
    const float* ow   = (const float*)d_in[2];
    const float* ob   = (const float*)d_in[3];
    const float* dw   = (const float*)d_in[4];
    const float* db   = (const float*)d_in[5];
    float* out = (float*)d_out;
    float* out_feat = out;                 // [4,64,96,96]
    float* out_diff = out + Bb * IMG;      // [4,64,96,96]

    float* offbuf; cudaGetSymbolAddress((void**)&offbuf, g_offset);
    float* wT;     cudaGetSymbolAddress((void**)&wT, g_wT);

    // 1) diff
    diff_kernel<<<(Bb * IMG + 255) / 256, 256>>>(ref, dist, out_diff);
    // 2) offset conv
    offset_conv_kernel<<<NPIX / 256, 256>>>(ref, ow, ob, offbuf);
    // 3) weight transpose
    wtrans_kernel<<<(KTOT * Oo + 255) / 256, 256>>>(dw, wT);
    // 4) deformable conv + bias + relu
    deform_kernel<<<NPIX / 64, 256>>>(ref, dist, out_diff, db, out_feat);
}